// round 15
// baseline (speedup 1.0000x reference)
#include <cuda_runtime.h>

#define SEQ 512
#define HIDDEN 512
#define HD 64
#define NPART 8

// ---------------------------------------------------------------------------
// Scratch (static __device__, no allocation)
// ---------------------------------------------------------------------------
__device__ unsigned g_Xh[SEQ * 256], g_Xl[SEQ * 256];
__device__ unsigned g_Wqh[SEQ * 256], g_Wql[SEQ * 256];
__device__ unsigned g_Wkh[SEQ * 256], g_Wkl[SEQ * 256];
__device__ unsigned g_Wvh[SEQ * 256], g_Wvl[SEQ * 256];
__device__ unsigned g_Woh[SEQ * 256], g_Wol[SEQ * 256];
__device__ float    g_q[SEQ * HIDDEN], g_k[SEQ * HIDDEN], g_v[SEQ * HIDDEN];
__device__ unsigned g_qh[SEQ * 256], g_ql[SEQ * 256];
__device__ unsigned g_kh[SEQ * 256], g_kl[SEQ * 256];
__device__ float    g_ctx[NPART][SEQ * HIDDEN];
__device__ unsigned g_Ch[SEQ * 256], g_Cl[SEQ * 256];
__device__ unsigned g_cnt[64];     // (i-tile, head) completion counters

// ---------------------------------------------------------------------------
// helpers
// ---------------------------------------------------------------------------
__device__ __forceinline__ void split2(float x0, float x1, unsigned& hi, unsigned& lo)
{
    unsigned u0 = __float_as_uint(x0), u1 = __float_as_uint(x1);
    unsigned h;
    asm("prmt.b32 %0, %1, %2, 0x7632;" : "=r"(h) : "r"(u0), "r"(u1));
    float l0 = x0 - __uint_as_float(u0 & 0xFFFF0000u);
    float l1 = x1 - __uint_as_float(u1 & 0xFFFF0000u);
    unsigned lp;
    asm("cvt.rn.bf16x2.f32 %0, %1, %2;" : "=r"(lp) : "f"(l1), "f"(l0));
    hi = h; lo = lp;
}

__device__ __forceinline__ void mma_bf16(float* c,
    unsigned a0, unsigned a1, unsigned a2, unsigned a3, unsigned b0, unsigned b1)
{
    asm("mma.sync.aligned.m16n8k16.row.col.f32.bf16.bf16.f32 "
        "{%0,%1,%2,%3}, {%4,%5,%6,%7}, {%8,%9}, {%0,%1,%2,%3};"
        : "+f"(c[0]), "+f"(c[1]), "+f"(c[2]), "+f"(c[3])
        : "r"(a0), "r"(a1), "r"(a2), "r"(a3), "r"(b0), "r"(b1));
}

__device__ __forceinline__ void ldsm4(unsigned& r0, unsigned& r1,
                                      unsigned& r2, unsigned& r3, unsigned addr)
{
    asm volatile("ldmatrix.sync.aligned.m8n8.x4.shared.b16 {%0,%1,%2,%3}, [%4];"
        : "=r"(r0), "=r"(r1), "=r"(r2), "=r"(r3) : "r"(addr));
}

__device__ __forceinline__ void cp16(void* dst, const void* src)
{
    unsigned d = (unsigned)__cvta_generic_to_shared(dst);
    asm volatile("cp.async.cg.shared.global [%0], [%1], 16;" :: "r"(d), "l"(src));
}
#define CP_COMMIT() asm volatile("cp.async.commit_group;")

__device__ __forceinline__ void fma2_acc(unsigned long long& acc, float a, float b,
                                         unsigned long long one2)
{
    asm("{\n\t.reg .b64 p;\n\tmov.b64 p, {%1,%2};\n\tfma.rn.f32x2 %0, p, %3, %0;\n\t}"
        : "+l"(acc) : "f"(a), "f"(b), "l"(one2));
}
__device__ __forceinline__ void add2_acc(unsigned long long& acc, float a, float b)
{
    asm("{\n\t.reg .b64 p;\n\tmov.b64 p, {%1,%2};\n\tadd.rn.f32x2 %0, %0, p;\n\t}"
        : "+l"(acc) : "f"(a), "f"(b));
}
__device__ __forceinline__ void unpack2(unsigned long long v, float& lo, float& hi)
{
    asm("mov.b64 {%0,%1}, %2;" : "=f"(lo), "=f"(hi) : "l"(v));
}

// ---------------------------------------------------------------------------
// Convert: split 5 f32 matrices into packed hi/lo planes; also zeroes the
// fused-kernel group counters (runs before fused every replay).
// float4 per thread, grid (256,1,5) x 256.
// ---------------------------------------------------------------------------
__global__ __launch_bounds__(256) void convert_kernel(
    const float* __restrict__ X, const float* __restrict__ Wq,
    const float* __restrict__ Wk, const float* __restrict__ Wv,
    const float* __restrict__ Wo)
{
    if (blockIdx.z == 0 && blockIdx.x == 0 && threadIdx.x < 64)
        g_cnt[threadIdx.x] = 0;

    const float* src; unsigned* dh; unsigned* dl;
    switch (blockIdx.z) {
        case 0:  src = X;  dh = g_Xh;  dl = g_Xl;  break;
        case 1:  src = Wq; dh = g_Wqh; dl = g_Wql; break;
        case 2:  src = Wk; dh = g_Wkh; dl = g_Wkl; break;
        case 3:  src = Wv; dh = g_Wvh; dl = g_Wvl; break;
        default: src = Wo; dh = g_Woh; dl = g_Wol; break;
    }
    int idx = blockIdx.x * 256 + threadIdx.x;
    float4 v = *(const float4*)(src + idx * 4);
    unsigned h0, l0, h1, l1;
    split2(v.x, v.y, h0, l0);
    split2(v.z, v.w, h1, l1);
    *(uint2*)(dh + idx * 2) = make_uint2(h0, h1);
    *(uint2*)(dl + idx * 2) = make_uint2(l0, l1);
}

// ---------------------------------------------------------------------------
// GEMM NT on pre-split planes: 32x32 tile, BK=16, 128 threads, cp.async
// 4-stage pipeline, pad-12 rows, ldmatrix.x4 fragment loads.
// ---------------------------------------------------------------------------
__device__ __forceinline__ void gemm32(
    const unsigned* __restrict__ Aph, const unsigned* __restrict__ Apl,
    const unsigned* __restrict__ Bph, const unsigned* __restrict__ Bpl,
    const float* __restrict__ bias, float* __restrict__ out,
    unsigned* __restrict__ outh, unsigned* __restrict__ outl)
{
    __shared__ unsigned smA[4][2][32][12];
    __shared__ unsigned smB[4][2][32][12];

    int t = threadIdx.x;
    int row0 = blockIdx.y * 32, col0 = blockIdx.x * 32;
    int lane = t & 31, warp = t >> 5;
    int wm = warp >> 1, wn = warp & 1;
    int g = lane >> 2, tq = lane & 3;

    int p = t >> 6, lr = (t >> 1) & 31, half = t & 1;

    const unsigned* Asrc = (p ? Apl : Aph) + (row0 + lr) * 256 + half * 4;
    const unsigned* Bsrc = (p ? Bpl : Bph) + (col0 + lr) * 256 + half * 4;

    unsigned smA_u = (unsigned)__cvta_generic_to_shared(&smA[0][0][0][0]);
    unsigned smB_u = (unsigned)__cvta_generic_to_shared(&smB[0][0][0][0]);
    int arow = wm * 16 + (lane & 7) + ((lane >> 3) & 1) * 8;
    int aseg = (lane >> 4) * 4;
    int brow = wn * 16 + (lane & 7) + ((lane >> 4) & 1) * 8;
    int bseg = ((lane >> 3) & 1) * 4;
    unsigned aoffB = (arow * 12 + aseg) * 4;
    unsigned boffB = (brow * 12 + bseg) * 4;

    float acc[2][4];
#pragma unroll
    for (int nt = 0; nt < 2; nt++)
#pragma unroll
        for (int x = 0; x < 4; x++) acc[nt][x] = 0.0f;

#pragma unroll
    for (int s = 0; s < 3; s++) {
        cp16(&smA[s][p][lr][half * 4], Asrc + s * 8);
        cp16(&smB[s][p][lr][half * 4], Bsrc + s * 8);
        CP_COMMIT();
    }

#pragma unroll 1
    for (int kb = 0; kb < 32; kb++) {
        asm volatile("cp.async.wait_group 2;");
        __syncthreads();
        if (kb + 3 < 32) {
            int s = (kb + 3) & 3;
            cp16(&smA[s][p][lr][half * 4], Asrc + (kb + 3) * 8);
            cp16(&smB[s][p][lr][half * 4], Bsrc + (kb + 3) * 8);
        }
        CP_COMMIT();

        int st = kb & 3;
        unsigned abase = smA_u + st * 3072 + aoffB;
        unsigned bbase = smB_u + st * 3072 + boffB;
        unsigned ah0, ah1, ah2, ah3, al0, al1, al2, al3;
        ldsm4(ah0, ah1, ah2, ah3, abase);
        ldsm4(al0, al1, al2, al3, abase + 1536);
        unsigned bh00, bh10, bh01, bh11, bl00, bl10, bl01, bl11;
        ldsm4(bh00, bh10, bh01, bh11, bbase);
        ldsm4(bl00, bl10, bl01, bl11, bbase + 1536);

        mma_bf16(acc[0], ah0, ah1, ah2, ah3, bh00, bh10);
        mma_bf16(acc[0], ah0, ah1, ah2, ah3, bl00, bl10);
        mma_bf16(acc[0], al0, al1, al2, al3, bh00, bh10);
        mma_bf16(acc[1], ah0, ah1, ah2, ah3, bh01, bh11);
        mma_bf16(acc[1], ah0, ah1, ah2, ah3, bl01, bl11);
        mma_bf16(acc[1], al0, al1, al2, al3, bh01, bh11);
    }
    asm volatile("cp.async.wait_group 0;");

#pragma unroll
    for (int nt = 0; nt < 2; nt++) {
        int row = row0 + wm * 16 + g;
        int col = col0 + wn * 16 + nt * 8 + 2 * tq;
        float2 b2 = *(const float2*)(bias + col);
        float v0 = acc[nt][0] + b2.x, v1 = acc[nt][1] + b2.y;
        float v2 = acc[nt][2] + b2.x, v3 = acc[nt][3] + b2.y;
        *(float2*)(out + row * HIDDEN + col) = make_float2(v0, v1);
        *(float2*)(out + (row + 8) * HIDDEN + col) = make_float2(v2, v3);
        if (outh) {
            unsigned h, l;
            split2(v0, v1, h, l);
            outh[row * 256 + (col >> 1)] = h; outl[row * 256 + (col >> 1)] = l;
            split2(v2, v3, h, l);
            outh[(row + 8) * 256 + (col >> 1)] = h; outl[(row + 8) * 256 + (col >> 1)] = l;
        }
    }
}

__global__ __launch_bounds__(128) void qkv_mma_kernel(
    const float* __restrict__ bq, const float* __restrict__ bk,
    const float* __restrict__ bv)
{
    if (blockIdx.z == 0)
        gemm32(g_Xh, g_Xl, g_Wqh, g_Wql, bq, g_q, g_qh, g_ql);
    else if (blockIdx.z == 1)
        gemm32(g_Xh, g_Xl, g_Wkh, g_Wkl, bk, g_k, g_kh, g_kl);
    else
        gemm32(g_Xh, g_Xl, g_Wvh, g_Wvl, bv, g_v, (unsigned*)0, (unsigned*)0);
}

__global__ __launch_bounds__(128) void out_mma_kernel(
    const float* __restrict__ bo, float* __restrict__ out)
{
    gemm32(g_Ch, g_Cl, g_Woh, g_Wol, bo, out, (unsigned*)0, (unsigned*)0);
}

// ---------------------------------------------------------------------------
// FUSED inhibitor + last-CTA reduction.
// CTA = (i-tile 64, head, j-part 64), 256 threads, occ 4. Static smem 45568B.
// After writing its ctx partial, the last CTA of each (i-tile, head) group
// sums all 8 partials and emits the g_Ch/g_Cl planes (replaces reduce_kernel).
// ---------------------------------------------------------------------------
__global__ __launch_bounds__(256, 4) void fused_kernel(
    const float* __restrict__ mask, const float* __restrict__ gamma)
{
    __shared__ unsigned smq[2][64][36];
    __shared__ unsigned smk[2][32][36];
    __shared__ float vs[32][68];
    __shared__ float zst[32][68];
    __shared__ float zqs[64], zkms[64];
    __shared__ unsigned is_last;

    int t = threadIdx.x;
    int i0 = blockIdx.x * 64, head = blockIdx.y, jp = blockIdx.z;
    int j0 = jp * 64;

    // ---- cp.async: q planes, k0 planes, v0 ----
    int qp = t >> 7, qrow = (t >> 1) & 63, qhalf = t & 1;
    {
        const unsigned* src = (qp ? g_ql : g_qh) + (i0 + qrow) * 256 + head * 32 + qhalf * 16;
#pragma unroll
        for (int s = 0; s < 4; s++)
            cp16(&smq[qp][qrow][qhalf * 16 + s * 4], src + s * 4);
    }
    int kp = t >> 7, krow = (t >> 2) & 31, kq4 = t & 3;
    const unsigned* kplane = kp ? g_kl : g_kh;
    {
        const unsigned* src = kplane + (j0 + krow) * 256 + head * 32 + kq4 * 8;
        cp16(&smk[kp][krow][kq4 * 8], src);
        cp16(&smk[kp][krow][kq4 * 8 + 4], src + 4);
    }
    int vrow = t >> 3, vseg = t & 7;
    {
        const float* src = g_v + (j0 + vrow) * HIDDEN + head * HD + vseg * 8;
        cp16(&vs[vrow][vseg * 8], src);
        cp16(&vs[vrow][vseg * 8 + 4], src + 4);
    }
    CP_COMMIT();

    // ---- inline norms (overlap the cp.async fills) ----
    float gsd = gamma[0] * 8.0f;
    float coef = 15.0f / (16.0f * gsd);
    float zc = 12.0f / gsd;
    float m2c = -2.0f * coef;
    {
        int nr = t >> 2, ns = t & 3;
        const float* qsrc = g_q + (i0 + nr) * HIDDEN + head * HD + ns * 16;
        float s = 0.0f;
#pragma unroll
        for (int cc = 0; cc < 4; cc++) {
            float4 f = *(const float4*)(qsrc + cc * 4);
            s = fmaf(f.x, f.x, s); s = fmaf(f.y, f.y, s);
            s = fmaf(f.z, f.z, s); s = fmaf(f.w, f.w, s);
        }
        s += __shfl_xor_sync(0xFFFFFFFFu, s, 1);
        s += __shfl_xor_sync(0xFFFFFFFFu, s, 2);
        if (ns == 0) zqs[nr] = coef * s;

        const float* ksrc = g_k + (j0 + nr) * HIDDEN + head * HD + ns * 16;
        float sk = 0.0f;
#pragma unroll
        for (int cc = 0; cc < 4; cc++) {
            float4 f = *(const float4*)(ksrc + cc * 4);
            sk = fmaf(f.x, f.x, sk); sk = fmaf(f.y, f.y, sk);
            sk = fmaf(f.z, f.z, sk); sk = fmaf(f.w, f.w, sk);
        }
        sk += __shfl_xor_sync(0xFFFFFFFFu, sk, 1);
        sk += __shfl_xor_sync(0xFFFFFFFFu, sk, 2);
        if (ns == 0)
            zkms[nr] = fmaf(coef, sk, zc + (1.0f - mask[j0 + nr]) * 1e10f);
    }

    int lane = t & 31, warp = t >> 5;
    int wm = warp >> 1, wn = warp & 1;
    int g = lane >> 2, tq = lane & 3;
    int ig = t >> 4, kg = t & 15;

    const unsigned long long one2 = 0x3F8000003F800000ULL;
    unsigned long long acc2[4][2];
#pragma unroll
    for (int a = 0; a < 4; a++) { acc2[a][0] = 0ULL; acc2[a][1] = 0ULL; }
    unsigned long long accz01 = 0ULL, accz23 = 0ULL;

    asm volatile("cp.async.wait_group 0;");
    __syncthreads();   // B1: smq/smk0/vs0/zqs/zkms visible

    float zq0 = zqs[wm * 16 + g];
    float zq1 = zqs[wm * 16 + g + 8];

    auto do_z = [&](int c) {
        float za[2][4];
#pragma unroll
        for (int nt = 0; nt < 2; nt++)
#pragma unroll
            for (int x = 0; x < 4; x++) za[nt][x] = 0.0f;
        int r = wm * 16 + g;
#pragma unroll
        for (int kb = 0; kb < 4; kb++) {
            int base = kb * 8;
            unsigned ah0 = smq[0][r][base + tq],     ah1 = smq[0][r + 8][base + tq];
            unsigned ah2 = smq[0][r][base + tq + 4], ah3 = smq[0][r + 8][base + tq + 4];
            unsigned al0 = smq[1][r][base + tq],     al1 = smq[1][r + 8][base + tq];
            unsigned al2 = smq[1][r][base + tq + 4], al3 = smq[1][r + 8][base + tq + 4];
#pragma unroll
            for (int nt = 0; nt < 2; nt++) {
                int n = wn * 16 + nt * 8 + g;
                unsigned bh0 = smk[0][n][base + tq], bh1 = smk[0][n][base + tq + 4];
                unsigned bl0 = smk[1][n][base + tq], bl1 = smk[1][n][base + tq + 4];
                mma_bf16(za[nt], ah0, ah1, ah2, ah3, bh0, bh1);
                mma_bf16(za[nt], ah0, ah1, ah2, ah3, bl0, bl1);
                mma_bf16(za[nt], al0, al1, al2, al3, bh0, bh1);
            }
        }
#pragma unroll
        for (int nt = 0; nt < 2; nt++) {
            int col = wn * 16 + nt * 8 + 2 * tq;
            float2 zk = *(const float2*)(zkms + c * 32 + col);
            zst[col][r]         = fmaf(m2c, za[nt][0], zq0 + zk.x);
            zst[col + 1][r]     = fmaf(m2c, za[nt][1], zq0 + zk.y);
            zst[col][r + 8]     = fmaf(m2c, za[nt][2], zq1 + zk.x);
            zst[col + 1][r + 8] = fmaf(m2c, za[nt][3], zq1 + zk.y);
        }
    };

    auto do_accum = [&]() {
#pragma unroll 4
        for (int jj = 0; jj < 32; jj++) {
            float4 z4 = *(const float4*)&zst[jj][ig * 4];
            float4 v4 = *(const float4*)&vs[jj][kg * 4];
            add2_acc(accz01, z4.x, z4.y);
            add2_acc(accz23, z4.z, z4.w);
            float za[4] = {z4.x, z4.y, z4.z, z4.w};
#pragma unroll
            for (int a = 0; a < 4; a++) {
                float z = za[a];
                fma2_acc(acc2[a][0], fmaxf(v4.x, z), fmaxf(v4.y, z), one2);
                fma2_acc(acc2[a][1], fmaxf(v4.z, z), fmaxf(v4.w, z), one2);
            }
        }
    };

    // ---- chunk 0 ----
    do_z(0);
    __syncthreads();   // B2: zst ready; smk0 reads done
    {   // issue k1 (overlaps accum0)
        const unsigned* src = kplane + (j0 + 32 + krow) * 256 + head * 32 + kq4 * 8;
        cp16(&smk[kp][krow][kq4 * 8], src);
        cp16(&smk[kp][krow][kq4 * 8 + 4], src + 4);
        CP_COMMIT();
    }
    do_accum();
    __syncthreads();   // B3: accum0 done with vs and zst
    {   // issue v1 (overlaps z1)
        const float* src = g_v + (j0 + 32 + vrow) * HIDDEN + head * HD + vseg * 8;
        cp16(&vs[vrow][vseg * 8], src);
        cp16(&vs[vrow][vseg * 8 + 4], src + 4);
        CP_COMMIT();
    }

    // ---- chunk 1 ----
    asm volatile("cp.async.wait_group 1;");   // k1 landed
    __syncthreads();   // B4: smk1 visible
    do_z(1);
    asm volatile("cp.async.wait_group 0;");   // v1 landed
    __syncthreads();   // B5: zst + vs1 visible
    do_accum();

    float az[4];
    unpack2(accz01, az[0], az[1]);
    unpack2(accz23, az[2], az[3]);
#pragma unroll
    for (int a = 0; a < 4; a++) {
        float a0, a1, a2, a3;
        unpack2(acc2[a][0], a0, a1);
        unpack2(acc2[a][1], a2, a3);
        float* outp = g_ctx[jp] + (i0 + ig * 4 + a) * HIDDEN + head * HD + kg * 4;
        *(float4*)outp = make_float4(a0 - az[a], a1 - az[a], a2 - az[a], a3 - az[a]);
    }

    // ---- last-CTA reduction: sum 8 partials -> bf16 hi/lo planes ----
    __threadfence();                 // release our ctx partial
    if (t == 0) {
        unsigned old = atomicAdd(&g_cnt[blockIdx.x * 8 + head], 1u);
        is_last = (old == NPART - 1) ? 1u : 0u;
    }
    __syncthreads();
    if (is_last) {
        __threadfence();             // acquire all partials
        int row = t >> 2, kq = t & 3;          // 64 rows x 4 k-quarters
        int base = (i0 + row) * HIDDEN + head * HD + kq * 16;
#pragma unroll
        for (int cc = 0; cc < 4; cc++) {
            float4 s = *(const float4*)&g_ctx[0][base + cc * 4];
#pragma unroll
            for (int p = 1; p < NPART; p++) {
                float4 v = *(const float4*)&g_ctx[p][base + cc * 4];
                s.x += v.x; s.y += v.y; s.z += v.z; s.w += v.w;
            }
            unsigned h0, l0, h1, l1;
            split2(s.x, s.y, h0, l0);
            split2(s.z, s.w, h1, l1);
            int pcol = (i0 + row) * 256 + head * 32 + kq * 8 + cc * 2;
            *(uint2*)(g_Ch + pcol) = make_uint2(h0, h1);
            *(uint2*)(g_Cl + pcol) = make_uint2(l0, l1);
        }
    }
}

extern "C" void kernel_launch(void* const* d_in, const int* in_sizes, int n_in,
                              void* d_out, int out_size)
{
    const float* X     = (const float*)d_in[0];
    const float* mask  = (const float*)d_in[1];
    const float* Wq    = (const float*)d_in[2];
    const float* bq    = (const float*)d_in[3];
    const float* Wk    = (const float*)d_in[4];
    const float* bk    = (const float*)d_in[5];
    const float* Wv    = (const float*)d_in[6];
    const float* bv    = (const float*)d_in[7];
    const float* Wo    = (const float*)d_in[8];
    const float* bo    = (const float*)d_in[9];
    const float* gamma = (const float*)d_in[10];
    float* out = (float*)d_out;

    convert_kernel<<<dim3(256, 1, 5), 256>>>(X, Wq, Wk, Wv, Wo);
    qkv_mma_kernel<<<dim3(16, 16, 3), 128>>>(bq, bk, bv);
    fused_kernel<<<dim3(8, 8, NPART), 256>>>(mask, gamma);
    out_mma_kernel<<<dim3(16, 16), 128>>>(bo, out);
}

// round 16
// speedup vs baseline: 1.1120x; 1.1120x over previous
#include <cuda_runtime.h>

#define SEQ 512
#define HIDDEN 512
#define HD 64
#define NPART 8

// ---------------------------------------------------------------------------
// Scratch (static __device__, no allocation)
// ---------------------------------------------------------------------------
__device__ unsigned g_Xh[SEQ * 256], g_Xl[SEQ * 256];
__device__ unsigned g_Wqh[SEQ * 256], g_Wql[SEQ * 256];
__device__ unsigned g_Wkh[SEQ * 256], g_Wkl[SEQ * 256];
__device__ unsigned g_Wvh[SEQ * 256], g_Wvl[SEQ * 256];
__device__ unsigned g_Woh[SEQ * 256], g_Wol[SEQ * 256];
__device__ float    g_q[SEQ * HIDDEN], g_k[SEQ * HIDDEN], g_v[SEQ * HIDDEN];
__device__ unsigned g_qh[SEQ * 256], g_ql[SEQ * 256];
__device__ unsigned g_kh[SEQ * 256], g_kl[SEQ * 256];
__device__ float    g_ctx[NPART][SEQ * HIDDEN];
__device__ unsigned g_Ch[SEQ * 256], g_Cl[SEQ * 256];

// ---------------------------------------------------------------------------
// helpers
// ---------------------------------------------------------------------------
__device__ __forceinline__ void split2(float x0, float x1, unsigned& hi, unsigned& lo)
{
    unsigned u0 = __float_as_uint(x0), u1 = __float_as_uint(x1);
    unsigned h;
    asm("prmt.b32 %0, %1, %2, 0x7632;" : "=r"(h) : "r"(u0), "r"(u1));
    float l0 = x0 - __uint_as_float(u0 & 0xFFFF0000u);
    float l1 = x1 - __uint_as_float(u1 & 0xFFFF0000u);
    unsigned lp;
    asm("cvt.rn.bf16x2.f32 %0, %1, %2;" : "=r"(lp) : "f"(l1), "f"(l0));
    hi = h; lo = lp;
}

__device__ __forceinline__ void mma_bf16(float* c,
    unsigned a0, unsigned a1, unsigned a2, unsigned a3, unsigned b0, unsigned b1)
{
    asm("mma.sync.aligned.m16n8k16.row.col.f32.bf16.bf16.f32 "
        "{%0,%1,%2,%3}, {%4,%5,%6,%7}, {%8,%9}, {%0,%1,%2,%3};"
        : "+f"(c[0]), "+f"(c[1]), "+f"(c[2]), "+f"(c[3])
        : "r"(a0), "r"(a1), "r"(a2), "r"(a3), "r"(b0), "r"(b1));
}

__device__ __forceinline__ void ldsm4(unsigned& r0, unsigned& r1,
                                      unsigned& r2, unsigned& r3, unsigned addr)
{
    asm volatile("ldmatrix.sync.aligned.m8n8.x4.shared.b16 {%0,%1,%2,%3}, [%4];"
        : "=r"(r0), "=r"(r1), "=r"(r2), "=r"(r3) : "r"(addr));
}

__device__ __forceinline__ void cp16(void* dst, const void* src)
{
    unsigned d = (unsigned)__cvta_generic_to_shared(dst);
    asm volatile("cp.async.cg.shared.global [%0], [%1], 16;" :: "r"(d), "l"(src));
}
#define CP_COMMIT() asm volatile("cp.async.commit_group;")

__device__ __forceinline__ void fma2_acc(unsigned long long& acc, float a, float b,
                                         unsigned long long one2)
{
    asm("{\n\t.reg .b64 p;\n\tmov.b64 p, {%1,%2};\n\tfma.rn.f32x2 %0, p, %3, %0;\n\t}"
        : "+l"(acc) : "f"(a), "f"(b), "l"(one2));
}
__device__ __forceinline__ void add2_acc(unsigned long long& acc, float a, float b)
{
    asm("{\n\t.reg .b64 p;\n\tmov.b64 p, {%1,%2};\n\tadd.rn.f32x2 %0, %0, p;\n\t}"
        : "+l"(acc) : "f"(a), "f"(b));
}
__device__ __forceinline__ void unpack2(unsigned long long v, float& lo, float& hi)
{
    asm("mov.b64 {%0,%1}, %2;" : "=f"(lo), "=f"(hi) : "l"(v));
}

// ---------------------------------------------------------------------------
// Convert: split 5 f32 matrices into packed hi/lo planes.
// float4 per thread, grid (256,1,5) x 256.
// ---------------------------------------------------------------------------
__global__ __launch_bounds__(256) void convert_kernel(
    const float* __restrict__ X, const float* __restrict__ Wq,
    const float* __restrict__ Wk, const float* __restrict__ Wv,
    const float* __restrict__ Wo)
{
    const float* src; unsigned* dh; unsigned* dl;
    switch (blockIdx.z) {
        case 0:  src = X;  dh = g_Xh;  dl = g_Xl;  break;
        case 1:  src = Wq; dh = g_Wqh; dl = g_Wql; break;
        case 2:  src = Wk; dh = g_Wkh; dl = g_Wkl; break;
        case 3:  src = Wv; dh = g_Wvh; dl = g_Wvl; break;
        default: src = Wo; dh = g_Woh; dl = g_Wol; break;
    }
    int idx = blockIdx.x * 256 + threadIdx.x;
    float4 v = *(const float4*)(src + idx * 4);
    unsigned h0, l0, h1, l1;
    split2(v.x, v.y, h0, l0);
    split2(v.z, v.w, h1, l1);
    *(uint2*)(dh + idx * 2) = make_uint2(h0, h1);
    *(uint2*)(dl + idx * 2) = make_uint2(l0, l1);
}

// ---------------------------------------------------------------------------
// GEMM NT on pre-split planes: 32x32 tile, BK=16, 128 threads, cp.async
// 4-stage pipeline, pad-12 rows, ldmatrix.x4 fragment loads.
// DUAL accumulator chains: accA += Ah*Bh (1 mma/kb/nt);
// accB += Ah*Bl + Al*Bh (2 mma/kb/nt). 4 independent chains instead of 2
// 3-deep chains -> latency actually covered at 2 warps/SMSP.
// ---------------------------------------------------------------------------
__device__ __forceinline__ void gemm32(
    const unsigned* __restrict__ Aph, const unsigned* __restrict__ Apl,
    const unsigned* __restrict__ Bph, const unsigned* __restrict__ Bpl,
    const float* __restrict__ bias, float* __restrict__ out,
    unsigned* __restrict__ outh, unsigned* __restrict__ outl)
{
    __shared__ unsigned smA[4][2][32][12];
    __shared__ unsigned smB[4][2][32][12];

    int t = threadIdx.x;
    int row0 = blockIdx.y * 32, col0 = blockIdx.x * 32;
    int lane = t & 31, warp = t >> 5;
    int wm = warp >> 1, wn = warp & 1;
    int g = lane >> 2, tq = lane & 3;

    int p = t >> 6, lr = (t >> 1) & 31, half = t & 1;

    const unsigned* Asrc = (p ? Apl : Aph) + (row0 + lr) * 256 + half * 4;
    const unsigned* Bsrc = (p ? Bpl : Bph) + (col0 + lr) * 256 + half * 4;

    unsigned smA_u = (unsigned)__cvta_generic_to_shared(&smA[0][0][0][0]);
    unsigned smB_u = (unsigned)__cvta_generic_to_shared(&smB[0][0][0][0]);
    int arow = wm * 16 + (lane & 7) + ((lane >> 3) & 1) * 8;
    int aseg = (lane >> 4) * 4;
    int brow = wn * 16 + (lane & 7) + ((lane >> 4) & 1) * 8;
    int bseg = ((lane >> 3) & 1) * 4;
    unsigned aoffB = (arow * 12 + aseg) * 4;
    unsigned boffB = (brow * 12 + bseg) * 4;

    float accA[2][4], accB[2][4];
#pragma unroll
    for (int nt = 0; nt < 2; nt++)
#pragma unroll
        for (int x = 0; x < 4; x++) { accA[nt][x] = 0.0f; accB[nt][x] = 0.0f; }

#pragma unroll
    for (int s = 0; s < 3; s++) {
        cp16(&smA[s][p][lr][half * 4], Asrc + s * 8);
        cp16(&smB[s][p][lr][half * 4], Bsrc + s * 8);
        CP_COMMIT();
    }

#pragma unroll 1
    for (int kb = 0; kb < 32; kb++) {
        asm volatile("cp.async.wait_group 2;");
        __syncthreads();
        if (kb + 3 < 32) {
            int s = (kb + 3) & 3;
            cp16(&smA[s][p][lr][half * 4], Asrc + (kb + 3) * 8);
            cp16(&smB[s][p][lr][half * 4], Bsrc + (kb + 3) * 8);
        }
        CP_COMMIT();

        int st = kb & 3;
        unsigned abase = smA_u + st * 3072 + aoffB;
        unsigned bbase = smB_u + st * 3072 + boffB;
        unsigned ah0, ah1, ah2, ah3, al0, al1, al2, al3;
        ldsm4(ah0, ah1, ah2, ah3, abase);
        ldsm4(al0, al1, al2, al3, abase + 1536);
        unsigned bh00, bh10, bh01, bh11, bl00, bl10, bl01, bl11;
        ldsm4(bh00, bh10, bh01, bh11, bbase);
        ldsm4(bl00, bl10, bl01, bl11, bbase + 1536);

        // 4 independent accumulator chains
        mma_bf16(accA[0], ah0, ah1, ah2, ah3, bh00, bh10);
        mma_bf16(accA[1], ah0, ah1, ah2, ah3, bh01, bh11);
        mma_bf16(accB[0], ah0, ah1, ah2, ah3, bl00, bl10);
        mma_bf16(accB[1], ah0, ah1, ah2, ah3, bl01, bl11);
        mma_bf16(accB[0], al0, al1, al2, al3, bh00, bh10);
        mma_bf16(accB[1], al0, al1, al2, al3, bh01, bh11);
    }
    asm volatile("cp.async.wait_group 0;");

#pragma unroll
    for (int nt = 0; nt < 2; nt++) {
        int row = row0 + wm * 16 + g;
        int col = col0 + wn * 16 + nt * 8 + 2 * tq;
        float2 b2 = *(const float2*)(bias + col);
        float v0 = accA[nt][0] + accB[nt][0] + b2.x;
        float v1 = accA[nt][1] + accB[nt][1] + b2.y;
        float v2 = accA[nt][2] + accB[nt][2] + b2.x;
        float v3 = accA[nt][3] + accB[nt][3] + b2.y;
        *(float2*)(out + row * HIDDEN + col) = make_float2(v0, v1);
        *(float2*)(out + (row + 8) * HIDDEN + col) = make_float2(v2, v3);
        if (outh) {
            unsigned h, l;
            split2(v0, v1, h, l);
            outh[row * 256 + (col >> 1)] = h; outl[row * 256 + (col >> 1)] = l;
            split2(v2, v3, h, l);
            outh[(row + 8) * 256 + (col >> 1)] = h; outl[(row + 8) * 256 + (col >> 1)] = l;
        }
    }
}

__global__ __launch_bounds__(128) void qkv_mma_kernel(
    const float* __restrict__ bq, const float* __restrict__ bk,
    const float* __restrict__ bv)
{
    if (blockIdx.z == 0)
        gemm32(g_Xh, g_Xl, g_Wqh, g_Wql, bq, g_q, g_qh, g_ql);
    else if (blockIdx.z == 1)
        gemm32(g_Xh, g_Xl, g_Wkh, g_Wkl, bk, g_k, g_kh, g_kl);
    else
        gemm32(g_Xh, g_Xl, g_Wvh, g_Wvl, bv, g_v, (unsigned*)0, (unsigned*)0);
}

__global__ __launch_bounds__(128) void out_mma_kernel(
    const float* __restrict__ bo, float* __restrict__ out)
{
    gemm32(g_Ch, g_Cl, g_Woh, g_Wol, bo, out, (unsigned*)0, (unsigned*)0);
}

// ---------------------------------------------------------------------------
// FUSED inhibitor: CTA = (i-tile 64, head, j-part 64), 256 threads, occ 4.
// Static smem 45568B. (R13/R14 known-good form, unchanged.)
// ---------------------------------------------------------------------------
__global__ __launch_bounds__(256, 4) void fused_kernel(
    const float* __restrict__ mask, const float* __restrict__ gamma)
{
    __shared__ unsigned smq[2][64][36];
    __shared__ unsigned smk[2][32][36];
    __shared__ float vs[32][68];
    __shared__ float zst[32][68];
    __shared__ float zqs[64], zkms[64];

    int t = threadIdx.x;
    int i0 = blockIdx.x * 64, head = blockIdx.y, jp = blockIdx.z;
    int j0 = jp * 64;

    // ---- cp.async: q planes, k0 planes, v0 ----
    int qp = t >> 7, qrow = (t >> 1) & 63, qhalf = t & 1;
    {
        const unsigned* src = (qp ? g_ql : g_qh) + (i0 + qrow) * 256 + head * 32 + qhalf * 16;
#pragma unroll
        for (int s = 0; s < 4; s++)
            cp16(&smq[qp][qrow][qhalf * 16 + s * 4], src + s * 4);
    }
    int kp = t >> 7, krow = (t >> 2) & 31, kq4 = t & 3;
    const unsigned* kplane = kp ? g_kl : g_kh;
    {
        const unsigned* src = kplane + (j0 + krow) * 256 + head * 32 + kq4 * 8;
        cp16(&smk[kp][krow][kq4 * 8], src);
        cp16(&smk[kp][krow][kq4 * 8 + 4], src + 4);
    }
    int vrow = t >> 3, vseg = t & 7;
    {
        const float* src = g_v + (j0 + vrow) * HIDDEN + head * HD + vseg * 8;
        cp16(&vs[vrow][vseg * 8], src);
        cp16(&vs[vrow][vseg * 8 + 4], src + 4);
    }
    CP_COMMIT();

    // ---- inline norms (overlap the cp.async fills) ----
    float gsd = gamma[0] * 8.0f;
    float coef = 15.0f / (16.0f * gsd);
    float zc = 12.0f / gsd;
    float m2c = -2.0f * coef;
    {
        int nr = t >> 2, ns = t & 3;
        const float* qsrc = g_q + (i0 + nr) * HIDDEN + head * HD + ns * 16;
        float s = 0.0f;
#pragma unroll
        for (int cc = 0; cc < 4; cc++) {
            float4 f = *(const float4*)(qsrc + cc * 4);
            s = fmaf(f.x, f.x, s); s = fmaf(f.y, f.y, s);
            s = fmaf(f.z, f.z, s); s = fmaf(f.w, f.w, s);
        }
        s += __shfl_xor_sync(0xFFFFFFFFu, s, 1);
        s += __shfl_xor_sync(0xFFFFFFFFu, s, 2);
        if (ns == 0) zqs[nr] = coef * s;

        const float* ksrc = g_k + (j0 + nr) * HIDDEN + head * HD + ns * 16;
        float sk = 0.0f;
#pragma unroll
        for (int cc = 0; cc < 4; cc++) {
            float4 f = *(const float4*)(ksrc + cc * 4);
            sk = fmaf(f.x, f.x, sk); sk = fmaf(f.y, f.y, sk);
            sk = fmaf(f.z, f.z, sk); sk = fmaf(f.w, f.w, sk);
        }
        sk += __shfl_xor_sync(0xFFFFFFFFu, sk, 1);
        sk += __shfl_xor_sync(0xFFFFFFFFu, sk, 2);
        if (ns == 0)
            zkms[nr] = fmaf(coef, sk, zc + (1.0f - mask[j0 + nr]) * 1e10f);
    }

    int lane = t & 31, warp = t >> 5;
    int wm = warp >> 1, wn = warp & 1;
    int g = lane >> 2, tq = lane & 3;
    int ig = t >> 4, kg = t & 15;

    const unsigned long long one2 = 0x3F8000003F800000ULL;
    unsigned long long acc2[4][2];
#pragma unroll
    for (int a = 0; a < 4; a++) { acc2[a][0] = 0ULL; acc2[a][1] = 0ULL; }
    unsigned long long accz01 = 0ULL, accz23 = 0ULL;

    asm volatile("cp.async.wait_group 0;");
    __syncthreads();   // B1: smq/smk0/vs0/zqs/zkms visible

    float zq0 = zqs[wm * 16 + g];
    float zq1 = zqs[wm * 16 + g + 8];

    auto do_z = [&](int c) {
        float za[2][4];
#pragma unroll
        for (int nt = 0; nt < 2; nt++)
#pragma unroll
            for (int x = 0; x < 4; x++) za[nt][x] = 0.0f;
        int r = wm * 16 + g;
#pragma unroll
        for (int kb = 0; kb < 4; kb++) {
            int base = kb * 8;
            unsigned ah0 = smq[0][r][base + tq],     ah1 = smq[0][r + 8][base + tq];
            unsigned ah2 = smq[0][r][base + tq + 4], ah3 = smq[0][r + 8][base + tq + 4];
            unsigned al0 = smq[1][r][base + tq],     al1 = smq[1][r + 8][base + tq];
            unsigned al2 = smq[1][r][base + tq + 4], al3 = smq[1][r + 8][base + tq + 4];
#pragma unroll
            for (int nt = 0; nt < 2; nt++) {
                int n = wn * 16 + nt * 8 + g;
                unsigned bh0 = smk[0][n][base + tq], bh1 = smk[0][n][base + tq + 4];
                unsigned bl0 = smk[1][n][base + tq], bl1 = smk[1][n][base + tq + 4];
                mma_bf16(za[nt], ah0, ah1, ah2, ah3, bh0, bh1);
                mma_bf16(za[nt], ah0, ah1, ah2, ah3, bl0, bl1);
                mma_bf16(za[nt], al0, al1, al2, al3, bh0, bh1);
            }
        }
#pragma unroll
        for (int nt = 0; nt < 2; nt++) {
            int col = wn * 16 + nt * 8 + 2 * tq;
            float2 zk = *(const float2*)(zkms + c * 32 + col);
            zst[col][r]         = fmaf(m2c, za[nt][0], zq0 + zk.x);
            zst[col + 1][r]     = fmaf(m2c, za[nt][1], zq0 + zk.y);
            zst[col][r + 8]     = fmaf(m2c, za[nt][2], zq1 + zk.x);
            zst[col + 1][r + 8] = fmaf(m2c, za[nt][3], zq1 + zk.y);
        }
    };

    auto do_accum = [&]() {
#pragma unroll 4
        for (int jj = 0; jj < 32; jj++) {
            float4 z4 = *(const float4*)&zst[jj][ig * 4];
            float4 v4 = *(const float4*)&vs[jj][kg * 4];
            add2_acc(accz01, z4.x, z4.y);
            add2_acc(accz23, z4.z, z4.w);
            float za[4] = {z4.x, z4.y, z4.z, z4.w};
#pragma unroll
            for (int a = 0; a < 4; a++) {
                float z = za[a];
                fma2_acc(acc2[a][0], fmaxf(v4.x, z), fmaxf(v4.y, z), one2);
                fma2_acc(acc2[a][1], fmaxf(v4.z, z), fmaxf(v4.w, z), one2);
            }
        }
    };

    // ---- chunk 0 ----
    do_z(0);
    __syncthreads();   // B2: zst ready; smk0 reads done
    {   // issue k1 (overlaps accum0)
        const unsigned* src = kplane + (j0 + 32 + krow) * 256 + head * 32 + kq4 * 8;
        cp16(&smk[kp][krow][kq4 * 8], src);
        cp16(&smk[kp][krow][kq4 * 8 + 4], src + 4);
        CP_COMMIT();
    }
    do_accum();
    __syncthreads();   // B3: accum0 done with vs and zst
    {   // issue v1 (overlaps z1)
        const float* src = g_v + (j0 + 32 + vrow) * HIDDEN + head * HD + vseg * 8;
        cp16(&vs[vrow][vseg * 8], src);
        cp16(&vs[vrow][vseg * 8 + 4], src + 4);
        CP_COMMIT();
    }

    // ---- chunk 1 ----
    asm volatile("cp.async.wait_group 1;");   // k1 landed
    __syncthreads();   // B4: smk1 visible
    do_z(1);
    asm volatile("cp.async.wait_group 0;");   // v1 landed
    __syncthreads();   // B5: zst + vs1 visible
    do_accum();

    float az[4];
    unpack2(accz01, az[0], az[1]);
    unpack2(accz23, az[2], az[3]);
#pragma unroll
    for (int a = 0; a < 4; a++) {
        float a0, a1, a2, a3;
        unpack2(acc2[a][0], a0, a1);
        unpack2(acc2[a][1], a2, a3);
        float* outp = g_ctx[jp] + (i0 + ig * 4 + a) * HIDDEN + head * HD + kg * 4;
        *(float4*)outp = make_float4(a0 - az[a], a1 - az[a], a2 - az[a], a3 - az[a]);
    }
}

// ---------------------------------------------------------------------------
// Reduce 8 partials -> packed hi/lo planes. float2 per thread, grid 512x256.
// ---------------------------------------------------------------------------
__global__ __launch_bounds__(256) void reduce_kernel()
{
    int idx = blockIdx.x * 256 + threadIdx.x;
    float2 s = make_float2(0.0f, 0.0f);
#pragma unroll
    for (int p = 0; p < NPART; p++) {
        float2 v = *(const float2*)&g_ctx[p][idx * 2];
        s.x += v.x; s.y += v.y;
    }
    unsigned h, l; split2(s.x, s.y, h, l);
    g_Ch[idx] = h; g_Cl[idx] = l;
}

extern "C" void kernel_launch(void* const* d_in, const int* in_sizes, int n_in,
                              void* d_out, int out_size)
{
    const float* X     = (const float*)d_in[0];
    const float* mask  = (const float*)d_in[1];
    const float* Wq    = (const float*)d_in[2];
    const float* bq    = (const float*)d_in[3];
    const float* Wk    = (const float*)d_in[4];
    const float* bk    = (const float*)d_in[5];
    const float* Wv    = (const float*)d_in[6];
    const float* bv    = (const float*)d_in[7];
    const float* Wo    = (const float*)d_in[8];
    const float* bo    = (const float*)d_in[9];
    const float* gamma = (const float*)d_in[10];
    float* out = (float*)d_out;

    convert_kernel<<<dim3(256, 1, 5), 256>>>(X, Wq, Wk, Wv, Wo);
    qkv_mma_kernel<<<dim3(16, 16, 3), 128>>>(bq, bk, bv);
    fused_kernel<<<dim3(8, 8, NPART), 256>>>(mask, gamma);
    reduce_kernel<<<512, 256>>>();
    out_mma_kernel<<<dim3(16, 16), 128>>>(bo, out);
}